// round 5
// baseline (speedup 1.0000x reference)
#include <cuda_runtime.h>
#include <stdint.h>

#define NROWS   500000
#define NCOLS   64
#define NELEM   (NROWS * NCOLS)        // 32,000,000
#define NF4     (NELEM / 4)            // 8,000,000
#define NG      (NF4 / 4)              // 2,000,000 groups of 4 float4s
#define NBINS   31
#define BLOCK   256
#define BPSM    6
#define NBLK    (148 * BPSM)           // 888
#define G       (NBLK * BLOCK)         // 227,328

__device__ unsigned int g_hist_all[32];
__device__ unsigned int g_hist_t[32];
__device__ unsigned int g_done;

// hist[bin][tid] increment; offset = bin*1024 comes straight from float bits:
// y_bits = 0x4B400000 + bin, and (0x4B400000 << 10) mod 2^32 == 0.
__device__ __forceinline__ void binc(unsigned int* hrow, float x) {
    float t = x * -1.4426950408889634f;
    float e; asm("ex2.approx.f32 %0, %1;" : "=f"(e) : "f"(t));   // e^-x
    float d = e + 1.0f;
    float v; asm("rcp.approx.f32 %0, %1;" : "=f"(v) : "f"(d));   // sigmoid
    float z = fmaf(v, 30.0f, -0.5f);
    float y = z + 12582912.0f;                                   // +1.5*2^23
    unsigned int off = __float_as_uint(y) << 10;                 // bin*1024
    unsigned int* p = (unsigned int*)((char*)hrow + off);
    (*p)++;
}

__device__ __forceinline__ int bin_of(float x) {                 // rare path
    float t = x * -1.4426950408889634f;
    float e; asm("ex2.approx.f32 %0, %1;" : "=f"(e) : "f"(t));
    float d = e + 1.0f;
    float v; asm("rcp.approx.f32 %0, %1;" : "=f"(v) : "f"(d));
    float z = fmaf(v, 30.0f, -0.5f);
    float y = z + 12582912.0f;
    return __float_as_int(y) - 0x4B400000;
}

__global__ __launch_bounds__(BLOCK, BPSM)
void auc_kernel(const float4* __restrict__ o4, const int* __restrict__ tgt,
                float* __restrict__ out) {
    __shared__ unsigned int hist[NBINS * BLOCK];   // 31,744 B, conflict-free
    __shared__ unsigned int strue[32];
    __shared__ int s_last;

    const int tid = threadIdx.x;
    #pragma unroll
    for (int i = tid; i < NBINS * BLOCK; i += BLOCK) hist[i] = 0u;
    if (tid < 32) strue[tid] = 0u;
    __syncthreads();

    unsigned int* hrow = &hist[tid];

    // Each iter: 4 consecutive float4s = 16 consecutive elems, all in ONE row
    // (rows are 16 float4s; 4-aligned groups never straddle).
    for (int g = blockIdx.x * BLOCK + tid; g < NG; g += G) {
        const float4* p = o4 + 4u * (unsigned)g;
        float4 v0 = p[0];
        float4 v1 = p[1];
        float4 v2 = p[2];
        float4 v3 = p[3];
        int tg = __ldg(tgt + (g >> 2));            // 4 groups per row

        binc(hrow, v0.x); binc(hrow, v0.y); binc(hrow, v0.z); binc(hrow, v0.w);
        binc(hrow, v1.x); binc(hrow, v1.y); binc(hrow, v1.z); binc(hrow, v1.w);
        binc(hrow, v2.x); binc(hrow, v2.y); binc(hrow, v2.z); binc(hrow, v2.w);
        binc(hrow, v3.x); binc(hrow, v3.y); binc(hrow, v3.z); binc(hrow, v3.w);

        // true-class element lands in this 16-elem group with prob 1/4
        int m = (tg >> 2) - ((g & 3) << 2);        // which of my 4 float4s
        if ((unsigned)m < 4u) {
            float4 vm = (m & 2) ? ((m & 1) ? v3 : v2) : ((m & 1) ? v1 : v0);
            int c = tg & 3;
            float xs = (c & 2) ? ((c & 1) ? vm.w : vm.z)
                               : ((c & 1) ? vm.y : vm.x);
            atomicAdd(&strue[bin_of(xs)], 1u);
        }
    }
    __syncthreads();

    // block reduction -> global atomics
    int lane = tid & 31, wid = tid >> 5;           // 8 warps
    for (int b = wid; b < NBINS; b += (BLOCK / 32)) {
        unsigned int s = 0;
        #pragma unroll
        for (int k = 0; k < BLOCK / 32; k++) s += hist[b * BLOCK + k * 32 + lane];
        #pragma unroll
        for (int o = 16; o; o >>= 1) s += __shfl_down_sync(0xffffffffu, s, o);
        if (lane == 0 && s) atomicAdd(&g_hist_all[b], s);
    }
    if (tid < NBINS) {
        unsigned int s = strue[tid];
        if (s) atomicAdd(&g_hist_t[tid], s);
    }

    // last-block finalize
    if (tid == 0) {
        __threadfence();
        unsigned int prev = atomicAdd(&g_done, 1u);
        s_last = (prev == gridDim.x - 1);
    }
    __syncthreads();
    if (s_last && tid == 0) {
        __threadfence();
        volatile unsigned int* vha = g_hist_all;
        volatile unsigned int* vht = g_hist_t;
        double ht[NBINS], ha[NBINS], trues = 0.0;
        for (int b = 0; b < NBINS; b++) {
            ht[b] = (double)vht[b];
            ha[b] = (double)vha[b];
            trues += ht[b];
        }
        double falses = (double)NELEM - trues;

        double tp_asc[30], fp_asc[30], ct = 0.0, cf = 0.0;
        for (int j = 0; j < 30; j++) {
            ct += ht[j];
            cf += (ha[j] - ht[j]);
            tp_asc[j] = trues  - ct;
            fp_asc[j] = falses - cf;
        }
        const double eps = 1e-8;
        double area = 0.0, pt = 0.0, pf = 0.0;
        for (int i = 0; i < 30; i++) {
            double tpr = tp_asc[29 - i] / (trues  + eps);
            double fpr = fp_asc[29 - i] / (falses + eps);
            double wdt = fabs(fpr - pf);
            double mn = fmin(tpr, pt), mx = fmax(tpr, pt);
            area += wdt * mn + 0.5 * wdt * (mx - mn);
            pt = tpr; pf = fpr;
        }
        out[0] = (float)area;

        for (int b = 0; b < 32; b++) { g_hist_all[b] = 0u; g_hist_t[b] = 0u; }
        g_done = 0u;
    }
}

extern "C" void kernel_launch(void* const* d_in, const int* in_sizes, int n_in,
                              void* d_out, int out_size) {
    const float* output = (const float*)d_in[0];
    const int*   target = (const int*)d_in[1];
    if (n_in >= 2 && in_sizes[0] == NROWS && in_sizes[1] == NELEM) {
        output = (const float*)d_in[1];
        target = (const int*)d_in[0];
    }
    auc_kernel<<<NBLK, BLOCK>>>((const float4*)output, target, (float*)d_out);
}